// round 2
// baseline (speedup 1.0000x reference)
#include <cuda_runtime.h>
#include <math.h>

#define BATCH 2
#define SEQ   2048
#define HEADS 8
#define DK    64
#define DM    512
#define ROWS  (BATCH*SEQ)        // 4096
#define NEGV  (-1e9f)

// ---- scratch (device globals; no allocation allowed) ----
__device__ float g_q[BATCH*HEADS*SEQ*DK];      // [b][h][s][d]
__device__ float g_k[BATCH*HEADS*SEQ*DK];
__device__ float g_v[BATCH*HEADS*SEQ*DK];
__device__ float g_attn[ROWS*DM];              // [b*S+s][h*64+d]

// ============================================================
// GEMM: C[m][n] = sum_k X[m][k]*W[n][k] + bias[n]
// 64x64 block tile, TK=32, 256 threads, 4x4 microtile.
// Writer functor selected by template-ish flag.
// ============================================================
__global__ void __launch_bounds__(256) qkv_proj_kernel(
    const float* __restrict__ xq, const float* __restrict__ xk, const float* __restrict__ xv,
    const float* __restrict__ Wq, const float* __restrict__ Wk, const float* __restrict__ Wv,
    const float* __restrict__ bq, const float* __restrict__ bk, const float* __restrict__ bv)
{
    const float* X; const float* W; const float* bias; float* out;
    if (blockIdx.z == 0)      { X = xq; W = Wq; bias = bq; out = g_q; }
    else if (blockIdx.z == 1) { X = xk; W = Wk; bias = bk; out = g_k; }
    else                      { X = xv; W = Wv; bias = bv; out = g_v; }

    __shared__ float As[64][33];
    __shared__ float Bs[64][33];

    const int m0 = blockIdx.y * 64;
    const int n0 = blockIdx.x * 64;
    const int tid = threadIdx.x;
    const int tx = tid & 15, ty = tid >> 4;
    const int lr = tid >> 3;            // 0..31
    const int lc = (tid & 7) * 4;       // 0..28

    float acc[4][4] = {};

    for (int k0 = 0; k0 < DM; k0 += 32) {
        #pragma unroll
        for (int rr = 0; rr < 2; rr++) {
            int r = lr + rr * 32;
            float4 a = *(const float4*)(X + (size_t)(m0 + r) * DM + k0 + lc);
            As[r][lc+0] = a.x; As[r][lc+1] = a.y; As[r][lc+2] = a.z; As[r][lc+3] = a.w;
            float4 b = *(const float4*)(W + (size_t)(n0 + r) * DM + k0 + lc);
            Bs[r][lc+0] = b.x; Bs[r][lc+1] = b.y; Bs[r][lc+2] = b.z; Bs[r][lc+3] = b.w;
        }
        __syncthreads();
        #pragma unroll
        for (int kk = 0; kk < 32; kk++) {
            float a[4], b[4];
            #pragma unroll
            for (int i = 0; i < 4; i++) a[i] = As[ty*4+i][kk];
            #pragma unroll
            for (int j = 0; j < 4; j++) b[j] = Bs[tx*4+j][kk];
            #pragma unroll
            for (int i = 0; i < 4; i++)
                #pragma unroll
                for (int j = 0; j < 4; j++)
                    acc[i][j] = fmaf(a[i], b[j], acc[i][j]);
        }
        __syncthreads();
    }

    // epilogue: scatter into [b][h][s][d]
    #pragma unroll
    for (int i = 0; i < 4; i++) {
        int row = m0 + ty*4 + i;
        int b   = row >> 11;        // /SEQ
        int s   = row & (SEQ-1);
        #pragma unroll
        for (int j = 0; j < 4; j++) {
            int col = n0 + tx*4 + j;
            int h = col >> 6, d = col & 63;
            float v = acc[i][j] + bias[col];
            out[(((b*HEADS + h) * SEQ) + s) * DK + d] = v;
        }
    }
}

// ============================================================
// Flash attention (fp32): BQ=BK=64, online softmax, diag mask.
// grid (S/64, H, B), 256 threads (16x16), 4x4 microtile.
// ============================================================
#define SMEM_ATTN (4 * 64 * 65 * 4)

__global__ void __launch_bounds__(256) attn_kernel()
{
    extern __shared__ float sm[];
    float* Qs = sm;                 // [64][65]
    float* Ks = Qs + 64*65;
    float* Vs = Ks + 64*65;
    float* Ps = Vs + 64*65;

    const int qb = blockIdx.x;
    const int h  = blockIdx.y;
    const int b  = blockIdx.z;

    const float* Q = g_q + (size_t)(b*HEADS + h) * SEQ * DK;
    const float* K = g_k + (size_t)(b*HEADS + h) * SEQ * DK;
    const float* V = g_v + (size_t)(b*HEADS + h) * SEQ * DK;

    const int tid = threadIdx.x;
    const int tx = tid & 15, ty = tid >> 4;
    const int lr = tid >> 2;           // 0..63
    const int lc = (tid & 3) * 16;     // 0,16,32,48

    // load Q tile once
    {
        const float* src = Q + (size_t)(qb*64 + lr) * DK + lc;
        #pragma unroll
        for (int c = 0; c < 16; c += 4) {
            float4 v4 = *(const float4*)(src + c);
            Qs[lr*65 + lc + c + 0] = v4.x;
            Qs[lr*65 + lc + c + 1] = v4.y;
            Qs[lr*65 + lc + c + 2] = v4.z;
            Qs[lr*65 + lc + c + 3] = v4.w;
        }
    }

    float m_i[4], l_i[4], o[4][4];
    #pragma unroll
    for (int i = 0; i < 4; i++) {
        m_i[i] = -INFINITY; l_i[i] = 0.f;
        #pragma unroll
        for (int j = 0; j < 4; j++) o[i][j] = 0.f;
    }

    for (int kb = 0; kb < SEQ/64; kb++) {
        __syncthreads();   // previous iter's PV reads done before overwrite
        {
            const float* ksrc = K + (size_t)(kb*64 + lr) * DK + lc;
            const float* vsrc = V + (size_t)(kb*64 + lr) * DK + lc;
            #pragma unroll
            for (int c = 0; c < 16; c += 4) {
                float4 k4 = *(const float4*)(ksrc + c);
                Ks[lr*65 + lc + c + 0] = k4.x;
                Ks[lr*65 + lc + c + 1] = k4.y;
                Ks[lr*65 + lc + c + 2] = k4.z;
                Ks[lr*65 + lc + c + 3] = k4.w;
                float4 v4 = *(const float4*)(vsrc + c);
                Vs[lr*65 + lc + c + 0] = v4.x;
                Vs[lr*65 + lc + c + 1] = v4.y;
                Vs[lr*65 + lc + c + 2] = v4.z;
                Vs[lr*65 + lc + c + 3] = v4.w;
            }
        }
        __syncthreads();

        // scores S = Q K^T * scale
        float s[4][4] = {};
        #pragma unroll 8
        for (int kk = 0; kk < DK; kk++) {
            float a[4], kv[4];
            #pragma unroll
            for (int i = 0; i < 4; i++) a[i]  = Qs[(ty*4+i)*65 + kk];
            #pragma unroll
            for (int j = 0; j < 4; j++) kv[j] = Ks[(tx*4+j)*65 + kk];
            #pragma unroll
            for (int i = 0; i < 4; i++)
                #pragma unroll
                for (int j = 0; j < 4; j++)
                    s[i][j] = fmaf(a[i], kv[j], s[i][j]);
        }

        // scale + diagonal mask
        #pragma unroll
        for (int i = 0; i < 4; i++) {
            int qg = qb*64 + ty*4 + i;
            #pragma unroll
            for (int j = 0; j < 4; j++) {
                int kg = kb*64 + tx*4 + j;
                s[i][j] *= 0.125f;               // 1/sqrt(64)
                if (qg == kg) s[i][j] = NEGV;
            }
        }

        // online softmax update per row
        #pragma unroll
        for (int i = 0; i < 4; i++) {
            float mx = fmaxf(fmaxf(s[i][0], s[i][1]), fmaxf(s[i][2], s[i][3]));
            #pragma unroll
            for (int off = 8; off >= 1; off >>= 1)
                mx = fmaxf(mx, __shfl_xor_sync(0xffffffffu, mx, off, 16));
            float m_new = fmaxf(m_i[i], mx);
            float alpha = (m_i[i] == -INFINITY) ? 0.f : __expf(m_i[i] - m_new);
            float rs = 0.f;
            #pragma unroll
            for (int j = 0; j < 4; j++) {
                float p = __expf(s[i][j] - m_new);
                Ps[(ty*4+i)*65 + tx*4 + j] = p;
                rs += p;
            }
            #pragma unroll
            for (int off = 8; off >= 1; off >>= 1)
                rs += __shfl_xor_sync(0xffffffffu, rs, off, 16);
            l_i[i] = l_i[i] * alpha + rs;
            m_i[i] = m_new;
            #pragma unroll
            for (int j = 0; j < 4; j++) o[i][j] *= alpha;
        }
        __syncthreads();

        // O += P @ V   (thread owns rows ty*4+i, d-cols tx*4+j)
        #pragma unroll 8
        for (int kc = 0; kc < 64; kc++) {
            float p[4], v[4];
            #pragma unroll
            for (int i = 0; i < 4; i++) p[i] = Ps[(ty*4+i)*65 + kc];
            #pragma unroll
            for (int j = 0; j < 4; j++) v[j] = Vs[kc*65 + tx*4 + j];
            #pragma unroll
            for (int i = 0; i < 4; i++)
                #pragma unroll
                for (int j = 0; j < 4; j++)
                    o[i][j] = fmaf(p[i], v[j], o[i][j]);
        }
    }

    // finalize: divide by l, write [b*S+s][h*64+d]
    #pragma unroll
    for (int i = 0; i < 4; i++) {
        float inv_l = 1.f / l_i[i];
        int srow = qb*64 + ty*4 + i;
        #pragma unroll
        for (int j = 0; j < 4; j++) {
            int d = tx*4 + j;
            g_attn[(size_t)(b*SEQ + srow) * DM + h*DK + d] = o[i][j] * inv_l;
        }
    }
}

// ============================================================
// Output projection: out = g_attn @ Wo^T + bo
// ============================================================
__global__ void __launch_bounds__(256) out_proj_kernel(
    const float* __restrict__ Wo, const float* __restrict__ bo, float* __restrict__ out)
{
    __shared__ float As[64][33];
    __shared__ float Bs[64][33];

    const int m0 = blockIdx.y * 64;
    const int n0 = blockIdx.x * 64;
    const int tid = threadIdx.x;
    const int tx = tid & 15, ty = tid >> 4;
    const int lr = tid >> 3;
    const int lc = (tid & 7) * 4;

    float acc[4][4] = {};

    for (int k0 = 0; k0 < DM; k0 += 32) {
        #pragma unroll
        for (int rr = 0; rr < 2; rr++) {
            int r = lr + rr * 32;
            float4 a = *(const float4*)(g_attn + (size_t)(m0 + r) * DM + k0 + lc);
            As[r][lc+0] = a.x; As[r][lc+1] = a.y; As[r][lc+2] = a.z; As[r][lc+3] = a.w;
            float4 b = *(const float4*)(Wo + (size_t)(n0 + r) * DM + k0 + lc);
            Bs[r][lc+0] = b.x; Bs[r][lc+1] = b.y; Bs[r][lc+2] = b.z; Bs[r][lc+3] = b.w;
        }
        __syncthreads();
        #pragma unroll
        for (int kk = 0; kk < 32; kk++) {
            float a[4], b[4];
            #pragma unroll
            for (int i = 0; i < 4; i++) a[i] = As[ty*4+i][kk];
            #pragma unroll
            for (int j = 0; j < 4; j++) b[j] = Bs[tx*4+j][kk];
            #pragma unroll
            for (int i = 0; i < 4; i++)
                #pragma unroll
                for (int j = 0; j < 4; j++)
                    acc[i][j] = fmaf(a[i], b[j], acc[i][j]);
        }
        __syncthreads();
    }

    #pragma unroll
    for (int i = 0; i < 4; i++) {
        int row = m0 + ty*4 + i;
        #pragma unroll
        for (int j = 0; j < 4; j++) {
            int col = n0 + tx*4 + j;
            out[(size_t)row * DM + col] = acc[i][j] + bo[col];
        }
    }
}

// ============================================================
extern "C" void kernel_launch(void* const* d_in, const int* in_sizes, int n_in,
                              void* d_out, int out_size)
{
    const float* q  = (const float*)d_in[0];
    const float* k  = (const float*)d_in[1];
    const float* v  = (const float*)d_in[2];
    const float* Wq = (const float*)d_in[3];
    const float* bq = (const float*)d_in[4];
    const float* Wk = (const float*)d_in[5];
    const float* bk = (const float*)d_in[6];
    const float* Wv = (const float*)d_in[7];
    const float* bv = (const float*)d_in[8];
    const float* Wo = (const float*)d_in[9];
    const float* bo = (const float*)d_in[10];
    float* out = (float*)d_out;

    cudaFuncSetAttribute(attn_kernel, cudaFuncAttributeMaxDynamicSharedMemorySize, SMEM_ATTN);

    qkv_proj_kernel<<<dim3(DM/64, ROWS/64, 3), 256>>>(q, k, v, Wq, Wk, Wv, bq, bk, bv);
    attn_kernel<<<dim3(SEQ/64, HEADS, BATCH), 256, SMEM_ATTN>>>();
    out_proj_kernel<<<dim3(DM/64, ROWS/64, 1), 256>>>(Wo, bo, out);
}

// round 4
// speedup vs baseline: 2.0420x; 2.0420x over previous
#include <cuda_runtime.h>
#include <math.h>
#include <stdint.h>

#define BATCH 2
#define SEQ   2048
#define HEADS 8
#define DK    64
#define DM    512
#define ROWS  (BATCH*SEQ)        // 4096
#define NEGV  (-1e9f)

// ---- scratch (device globals; no allocation allowed) ----
__device__ float g_q[BATCH*HEADS*SEQ*DK];      // [b][h][s][d]
__device__ float g_k[BATCH*HEADS*SEQ*DK];
__device__ float g_v[BATCH*HEADS*SEQ*DK];
__device__ float g_attn[ROWS*DM];              // [b*S+s][h*64+d]

// ============================================================
// helpers
// ============================================================
__device__ __forceinline__ float tf32_rn(float f) {
    uint32_t u;
    asm("cvt.rna.tf32.f32 %0, %1;" : "=r"(u) : "f"(f));
    return __uint_as_float(u);
}

// D = A(16x8 tf32) * B(8x8 tf32) + D, fp32 accum
__device__ __forceinline__ void mma_tf32(float c[4], const uint32_t a[4],
                                         uint32_t b0, uint32_t b1) {
    asm volatile(
        "mma.sync.aligned.m16n8k8.row.col.f32.tf32.tf32.f32 "
        "{%0,%1,%2,%3}, {%4,%5,%6,%7}, {%8,%9}, {%0,%1,%2,%3};"
        : "+f"(c[0]), "+f"(c[1]), "+f"(c[2]), "+f"(c[3])
        : "r"(a[0]), "r"(a[1]), "r"(a[2]), "r"(a[3]), "r"(b0), "r"(b1));
}

// ============================================================
// Projection GEMM via mma.sync, 3-mma split-TF32 (fp32-accurate).
// C[m][n] = sum_k X[m][k] * W[n][k] + bias[n]
// block tile 128m x 64n, 8 warps (each m16 x n64), K-chunk 32.
// smem pitch 36 floats -> frag loads conflict-free (4r+c mod 32).
// ============================================================
#define PG_P 36
#define PG_FLOATS (4608 + 4608 + 2304 + 2304)
#define PG_DYN (PG_FLOATS * 4)

__device__ __forceinline__ void gemm_mma_body(
    const float* __restrict__ X, const float* __restrict__ W,
    const float* __restrict__ bias, float* __restrict__ out,
    int scatter, float* sm)
{
    float* Xh = sm;
    float* Xl = sm + 4608;
    float* Wh = sm + 9216;
    float* Wl = sm + 11520;

    const int tid = threadIdx.x;
    const int wid = tid >> 5, lane = tid & 31;
    const int gr = lane >> 2, gc = lane & 3;
    const int m0 = blockIdx.y * 128;
    const int n0 = blockIdx.x * 64;

    float acc[8][4] = {};

    for (int kc = 0; kc < DM; kc += 32) {
        __syncthreads();   // previous chunk fully consumed
        // X tile: 128 x 32
        #pragma unroll
        for (int i = 0; i < 4; i++) {
            int idx = tid + i * 256;           // 1024 float4
            int r = idx >> 3, c = (idx & 7) * 4;
            float4 v = *(const float4*)(X + (size_t)(m0 + r) * DM + kc + c);
            float hx = tf32_rn(v.x), hy = tf32_rn(v.y), hz = tf32_rn(v.z), hw = tf32_rn(v.w);
            int o = r * PG_P + c;
            Xh[o] = hx; Xh[o+1] = hy; Xh[o+2] = hz; Xh[o+3] = hw;
            Xl[o]   = tf32_rn(v.x - hx);
            Xl[o+1] = tf32_rn(v.y - hy);
            Xl[o+2] = tf32_rn(v.z - hz);
            Xl[o+3] = tf32_rn(v.w - hw);
        }
        // W tile: 64 x 32
        #pragma unroll
        for (int i = 0; i < 2; i++) {
            int idx = tid + i * 256;           // 512 float4
            int r = idx >> 3, c = (idx & 7) * 4;
            float4 v = *(const float4*)(W + (size_t)(n0 + r) * DM + kc + c);
            float hx = tf32_rn(v.x), hy = tf32_rn(v.y), hz = tf32_rn(v.z), hw = tf32_rn(v.w);
            int o = r * PG_P + c;
            Wh[o] = hx; Wh[o+1] = hy; Wh[o+2] = hz; Wh[o+3] = hw;
            Wl[o]   = tf32_rn(v.x - hx);
            Wl[o+1] = tf32_rn(v.y - hy);
            Wl[o+2] = tf32_rn(v.z - hz);
            Wl[o+3] = tf32_rn(v.w - hw);
        }
        __syncthreads();

        #pragma unroll
        for (int ks = 0; ks < 4; ks++) {
            const int k0 = ks * 8;
            uint32_t ah[4], al[4];
            int a0 = (wid * 16 + gr) * PG_P + k0 + gc;
            ah[0] = __float_as_uint(Xh[a0]);
            ah[1] = __float_as_uint(Xh[a0 + 8 * PG_P]);
            ah[2] = __float_as_uint(Xh[a0 + 4]);
            ah[3] = __float_as_uint(Xh[a0 + 8 * PG_P + 4]);
            al[0] = __float_as_uint(Xl[a0]);
            al[1] = __float_as_uint(Xl[a0 + 8 * PG_P]);
            al[2] = __float_as_uint(Xl[a0 + 4]);
            al[3] = __float_as_uint(Xl[a0 + 8 * PG_P + 4]);
            #pragma unroll
            for (int t = 0; t < 8; t++) {
                int br = (t * 8 + gr) * PG_P + k0 + gc;
                uint32_t bh0 = __float_as_uint(Wh[br]);
                uint32_t bh1 = __float_as_uint(Wh[br + 4]);
                uint32_t bl0 = __float_as_uint(Wl[br]);
                uint32_t bl1 = __float_as_uint(Wl[br + 4]);
                mma_tf32(acc[t], ah, bh0, bh1);
                mma_tf32(acc[t], al, bh0, bh1);
                mma_tf32(acc[t], ah, bl0, bl1);
            }
        }
    }

    // epilogue: C layout c0/c1 -> (row gr, cols 2gc,2gc+1), c2/c3 -> row gr+8
    const int r0 = m0 + wid * 16 + gr;
    #pragma unroll
    for (int t = 0; t < 8; t++) {
        int col = n0 + t * 8 + gc * 2;
        float b0v = bias[col], b1v = bias[col + 1];
        float2 v0 = make_float2(acc[t][0] + b0v, acc[t][1] + b1v);
        float2 v1 = make_float2(acc[t][2] + b0v, acc[t][3] + b1v);
        if (scatter) {
            int hh = col >> 6, d = col & 63;
            int b_ = r0 >> 11, s_ = r0 & (SEQ - 1);
            *(float2*)(out + ((size_t)(b_ * HEADS + hh) * SEQ + s_) * DK + d) = v0;
            int r1 = r0 + 8;
            b_ = r1 >> 11; s_ = r1 & (SEQ - 1);
            *(float2*)(out + ((size_t)(b_ * HEADS + hh) * SEQ + s_) * DK + d) = v1;
        } else {
            *(float2*)(out + (size_t)r0 * DM + col) = v0;
            *(float2*)(out + (size_t)(r0 + 8) * DM + col) = v1;
        }
    }
}

__global__ void __launch_bounds__(256) qkv_gemm_kernel(
    const float* __restrict__ xq, const float* __restrict__ xk, const float* __restrict__ xv,
    const float* __restrict__ Wq, const float* __restrict__ Wk, const float* __restrict__ Wv,
    const float* __restrict__ bq, const float* __restrict__ bk, const float* __restrict__ bv)
{
    extern __shared__ float smf[];
    const float* X; const float* W; const float* bias; float* out;
    if (blockIdx.z == 0)      { X = xq; W = Wq; bias = bq; out = g_q; }
    else if (blockIdx.z == 1) { X = xk; W = Wk; bias = bk; out = g_k; }
    else                      { X = xv; W = Wv; bias = bv; out = g_v; }
    gemm_mma_body(X, W, bias, out, 1, smf);
}

__global__ void __launch_bounds__(256) out_gemm_kernel(
    const float* __restrict__ Wo, const float* __restrict__ bo, float* __restrict__ out)
{
    extern __shared__ float smf[];
    gemm_mma_body(g_attn, Wo, bo, out, 0, smf);
}

// ============================================================
// Flash attention with mma.sync tf32.
// BQ=128, BK=64, D=64. 8 warps, each owns m16 x (all 64 k-cols / d-cols).
// QK^T: 3-mma split (Q hi/lo, K hi/lo) -> fp32-accurate logits.
// PV:   1-mma (P tf32, V tf32) -> ~4e-4 stage error.
// pitches: Q/P 68 (4r+c), K 68, V 72 (8c+r) -> conflict-free frags.
// ============================================================
#define AT_PQ 68
#define AT_PK 68
#define AT_PV 72
// float offsets
#define AT_QH 0
#define AT_QL 8704
#define AT_KH 17408
#define AT_KL 21760
#define AT_V  26112
#define AT_P  30720
#define AT_FLOATS 39424
#define AT_DYN (AT_FLOATS * 4)

__global__ void __launch_bounds__(256) attn_kernel()
{
    extern __shared__ float sm[];
    float* Qh = sm + AT_QH;
    float* Ql = sm + AT_QL;
    float* Kh = sm + AT_KH;
    float* Kl = sm + AT_KL;
    float* Vs = sm + AT_V;
    float* Ps = sm + AT_P;

    const int qb = blockIdx.x;
    const int h  = blockIdx.y;
    const int b  = blockIdx.z;

    const float* Q = g_q + (size_t)(b * HEADS + h) * SEQ * DK;
    const float* K = g_k + (size_t)(b * HEADS + h) * SEQ * DK;
    const float* V = g_v + (size_t)(b * HEADS + h) * SEQ * DK;

    const int tid = threadIdx.x;
    const int wid = tid >> 5, lane = tid & 31;
    const int gr = lane >> 2, gc = lane & 3;
    const int mrow0 = wid * 16;

    // load Q tile (128 x 64) split hi/lo
    #pragma unroll
    for (int i = 0; i < 8; i++) {
        int idx = tid + i * 256;             // 2048 float4
        int r = idx >> 4, c = (idx & 15) * 4;
        float4 v = *(const float4*)(Q + (size_t)(qb * 128 + r) * DK + c);
        float hx = tf32_rn(v.x), hy = tf32_rn(v.y), hz = tf32_rn(v.z), hw = tf32_rn(v.w);
        int o = r * AT_PQ + c;
        Qh[o] = hx; Qh[o+1] = hy; Qh[o+2] = hz; Qh[o+3] = hw;
        Ql[o]   = tf32_rn(v.x - hx);
        Ql[o+1] = tf32_rn(v.y - hy);
        Ql[o+2] = tf32_rn(v.z - hz);
        Ql[o+3] = tf32_rn(v.w - hw);
    }

    float mrow[2] = { -INFINITY, -INFINITY };
    float lrow[2] = { 0.f, 0.f };
    float o_acc[8][4] = {};

    for (int kb = 0; kb < SEQ / 64; kb++) {
        __syncthreads();   // all warps finished reading K/V of prev iter
        // load K (hi/lo) and V tiles: 64 x 64 each
        #pragma unroll
        for (int i = 0; i < 4; i++) {
            int idx = tid + i * 256;         // 1024 float4
            int r = idx >> 4, c = (idx & 15) * 4;
            float4 kv = *(const float4*)(K + (size_t)(kb * 64 + r) * DK + c);
            float hx = tf32_rn(kv.x), hy = tf32_rn(kv.y), hz = tf32_rn(kv.z), hw = tf32_rn(kv.w);
            int ok = r * AT_PK + c;
            Kh[ok] = hx; Kh[ok+1] = hy; Kh[ok+2] = hz; Kh[ok+3] = hw;
            Kl[ok]   = tf32_rn(kv.x - hx);
            Kl[ok+1] = tf32_rn(kv.y - hy);
            Kl[ok+2] = tf32_rn(kv.z - hz);
            Kl[ok+3] = tf32_rn(kv.w - hw);
            float4 vv = *(const float4*)(V + (size_t)(kb * 64 + r) * DK + c);
            int ov = r * AT_PV + c;
            Vs[ov]   = tf32_rn(vv.x);
            Vs[ov+1] = tf32_rn(vv.y);
            Vs[ov+2] = tf32_rn(vv.z);
            Vs[ov+3] = tf32_rn(vv.w);
        }
        __syncthreads();

        // ---- scores: S = Q K^T (3-mma split over D=64) ----
        float s_acc[8][4] = {};
        #pragma unroll
        for (int ks = 0; ks < 8; ks++) {
            const int k0 = ks * 8;
            uint32_t ah[4], al[4];
            int a0 = (mrow0 + gr) * AT_PQ + k0 + gc;
            ah[0] = __float_as_uint(Qh[a0]);
            ah[1] = __float_as_uint(Qh[a0 + 8 * AT_PQ]);
            ah[2] = __float_as_uint(Qh[a0 + 4]);
            ah[3] = __float_as_uint(Qh[a0 + 8 * AT_PQ + 4]);
            al[0] = __float_as_uint(Ql[a0]);
            al[1] = __float_as_uint(Ql[a0 + 8 * AT_PQ]);
            al[2] = __float_as_uint(Ql[a0 + 4]);
            al[3] = __float_as_uint(Ql[a0 + 8 * AT_PQ + 4]);
            #pragma unroll
            for (int t = 0; t < 8; t++) {
                int br = (t * 8 + gr) * AT_PK + k0 + gc;
                uint32_t bh0 = __float_as_uint(Kh[br]);
                uint32_t bh1 = __float_as_uint(Kh[br + 4]);
                uint32_t bl0 = __float_as_uint(Kl[br]);
                uint32_t bl1 = __float_as_uint(Kl[br + 4]);
                mma_tf32(s_acc[t], ah, bh0, bh1);
                mma_tf32(s_acc[t], al, bh0, bh1);
                mma_tf32(s_acc[t], ah, bl0, bl1);
            }
        }

        // ---- scale + diag mask + online softmax ----
        const int qg0 = qb * 128 + mrow0 + gr;
        const int qg1 = qg0 + 8;
        float mx0 = -INFINITY, mx1 = -INFINITY;
        #pragma unroll
        for (int t = 0; t < 8; t++) {
            #pragma unroll
            for (int j = 0; j < 2; j++) {
                int colg = kb * 64 + t * 8 + gc * 2 + j;
                float v0 = s_acc[t][j] * 0.125f;
                if (colg == qg0) v0 = NEGV;
                s_acc[t][j] = v0;
                mx0 = fmaxf(mx0, v0);
                float v1 = s_acc[t][j + 2] * 0.125f;
                if (colg == qg1) v1 = NEGV;
                s_acc[t][j + 2] = v1;
                mx1 = fmaxf(mx1, v1);
            }
        }
        mx0 = fmaxf(mx0, __shfl_xor_sync(0xffffffffu, mx0, 1));
        mx0 = fmaxf(mx0, __shfl_xor_sync(0xffffffffu, mx0, 2));
        mx1 = fmaxf(mx1, __shfl_xor_sync(0xffffffffu, mx1, 1));
        mx1 = fmaxf(mx1, __shfl_xor_sync(0xffffffffu, mx1, 2));

        float mn0 = fmaxf(mrow[0], mx0);
        float mn1 = fmaxf(mrow[1], mx1);
        float al0 = (mrow[0] == -INFINITY) ? 0.f : __expf(mrow[0] - mn0);
        float al1 = (mrow[1] == -INFINITY) ? 0.f : __expf(mrow[1] - mn1);

        float rs0 = 0.f, rs1 = 0.f;
        #pragma unroll
        for (int t = 0; t < 8; t++) {
            float p00 = __expf(s_acc[t][0] - mn0);
            float p01 = __expf(s_acc[t][1] - mn0);
            float p10 = __expf(s_acc[t][2] - mn1);
            float p11 = __expf(s_acc[t][3] - mn1);
            rs0 += p00 + p01;
            rs1 += p10 + p11;
            int pc = t * 8 + gc * 2;
            *(float2*)(&Ps[(mrow0 + gr) * AT_PQ + pc]) =
                make_float2(tf32_rn(p00), tf32_rn(p01));
            *(float2*)(&Ps[(mrow0 + gr + 8) * AT_PQ + pc]) =
                make_float2(tf32_rn(p10), tf32_rn(p11));
        }
        rs0 += __shfl_xor_sync(0xffffffffu, rs0, 1);
        rs0 += __shfl_xor_sync(0xffffffffu, rs0, 2);
        rs1 += __shfl_xor_sync(0xffffffffu, rs1, 1);
        rs1 += __shfl_xor_sync(0xffffffffu, rs1, 2);

        lrow[0] = lrow[0] * al0 + rs0;
        lrow[1] = lrow[1] * al1 + rs1;
        mrow[0] = mn0;
        mrow[1] = mn1;
        #pragma unroll
        for (int t = 0; t < 8; t++) {
            o_acc[t][0] *= al0; o_acc[t][1] *= al0;
            o_acc[t][2] *= al1; o_acc[t][3] *= al1;
        }
        __syncwarp();    // P visible within warp

        // ---- O += P @ V ----
        #pragma unroll
        for (int ks = 0; ks < 8; ks++) {
            const int k0 = ks * 8;
            uint32_t a[4];
            int p0 = (mrow0 + gr) * AT_PQ + k0 + gc;
            a[0] = __float_as_uint(Ps[p0]);
            a[1] = __float_as_uint(Ps[p0 + 8 * AT_PQ]);
            a[2] = __float_as_uint(Ps[p0 + 4]);
            a[3] = __float_as_uint(Ps[p0 + 8 * AT_PQ + 4]);
            #pragma unroll
            for (int t = 0; t < 8; t++) {
                int vr = (k0 + gc) * AT_PV + t * 8 + gr;
                uint32_t b0 = __float_as_uint(Vs[vr]);
                uint32_t b1 = __float_as_uint(Vs[vr + 4 * AT_PV]);
                mma_tf32(o_acc[t], a, b0, b1);
            }
        }
    }

    // ---- finalize ----
    float inv0 = 1.f / lrow[0];
    float inv1 = 1.f / lrow[1];
    int s0 = qb * 128 + mrow0 + gr;
    #pragma unroll
    for (int t = 0; t < 8; t++) {
        int d = t * 8 + gc * 2;
        *(float2*)(g_attn + (size_t)(b * SEQ + s0) * DM + h * DK + d) =
            make_float2(o_acc[t][0] * inv0, o_acc[t][1] * inv0);
        *(float2*)(g_attn + (size_t)(b * SEQ + s0 + 8) * DM + h * DK + d) =
            make_float2(o_acc[t][2] * inv1, o_acc[t][3] * inv1);
    }
}

// ============================================================
extern "C" void kernel_launch(void* const* d_in, const int* in_sizes, int n_in,
                              void* d_out, int out_size)
{
    const float* q  = (const float*)d_in[0];
    const float* k  = (const float*)d_in[1];
    const float* v  = (const float*)d_in[2];
    const float* Wq = (const float*)d_in[3];
    const float* bq = (const float*)d_in[4];
    const float* Wk = (const float*)d_in[5];
    const float* bk = (const float*)d_in[6];
    const float* Wv = (const float*)d_in[7];
    const float* bv = (const float*)d_in[8];
    const float* Wo = (const float*)d_in[9];
    const float* bo = (const float*)d_in[10];
    float* out = (float*)d_out;

    cudaFuncSetAttribute(attn_kernel, cudaFuncAttributeMaxDynamicSharedMemorySize, AT_DYN);
    cudaFuncSetAttribute(qkv_gemm_kernel, cudaFuncAttributeMaxDynamicSharedMemorySize, PG_DYN);
    cudaFuncSetAttribute(out_gemm_kernel, cudaFuncAttributeMaxDynamicSharedMemorySize, PG_DYN);

    qkv_gemm_kernel<<<dim3(DM/64, ROWS/128, 3), 256, PG_DYN>>>(q, k, v, Wq, Wk, Wv, bq, bk, bv);
    attn_kernel<<<dim3(SEQ/128, HEADS, BATCH), 256, AT_DYN>>>();
    out_gemm_kernel<<<dim3(DM/64, ROWS/128, 1), 256, PG_DYN>>>(Wo, bo, out);
}

// round 5
// speedup vs baseline: 2.8338x; 1.3877x over previous
#include <cuda_runtime.h>
#include <math.h>
#include <stdint.h>

#define BATCH 2
#define SEQ   2048
#define HEADS 8
#define DK    64
#define DM    512
#define ROWS  (BATCH*SEQ)        // 4096
#define NEGV  (-1e9f)

// ---- scratch (device globals; no allocation allowed) ----
__device__ float g_q[BATCH*HEADS*SEQ*DK];      // [b][h][s][d]
__device__ float g_k[BATCH*HEADS*SEQ*DK];
__device__ float g_v[BATCH*HEADS*SEQ*DK];
__device__ float g_attn[ROWS*DM];              // [b*S+s][h*64+d]

// ============================================================
// helpers
// ============================================================
__device__ __forceinline__ float tf32_rn(float f) {
    uint32_t u;
    asm("cvt.rna.tf32.f32 %0, %1;" : "=r"(u) : "f"(f));
    return __uint_as_float(u);
}

// D = A(16x8 tf32) * B(8x8 tf32) + D, fp32 accum
__device__ __forceinline__ void mma_tf32(float c[4], const uint32_t a[4],
                                         uint32_t b0, uint32_t b1) {
    asm volatile(
        "mma.sync.aligned.m16n8k8.row.col.f32.tf32.tf32.f32 "
        "{%0,%1,%2,%3}, {%4,%5,%6,%7}, {%8,%9}, {%0,%1,%2,%3};"
        : "+f"(c[0]), "+f"(c[1]), "+f"(c[2]), "+f"(c[3])
        : "r"(a[0]), "r"(a[1]), "r"(a[2]), "r"(a[3]), "r"(b0), "r"(b1));
}

// ============================================================
// Projection GEMM via mma.sync, 2-mma split-TF32.
// C[m][n] = sum_k X[m][k] * W[n][k] + bias[n]
// A = X split hi/lo (exact); B = W single-rounded (rna).
// block tile 128m x 64n, 8 warps (each m16 x n64), K-chunk 32.
// ============================================================
#define PG_P 36
#define PG_FLOATS (4608 + 4608 + 2304)
#define PG_DYN (PG_FLOATS * 4)

__device__ __forceinline__ void gemm_mma_body(
    const float* __restrict__ X, const float* __restrict__ W,
    const float* __restrict__ bias, float* __restrict__ out,
    int scatter, float* sm)
{
    float* Xh = sm;
    float* Xl = sm + 4608;
    float* Wh = sm + 9216;

    const int tid = threadIdx.x;
    const int wid = tid >> 5, lane = tid & 31;
    const int gr = lane >> 2, gc = lane & 3;
    const int m0 = blockIdx.y * 128;
    const int n0 = blockIdx.x * 64;

    float acc[8][4] = {};

    for (int kc = 0; kc < DM; kc += 32) {
        __syncthreads();   // previous chunk fully consumed
        // X tile: 128 x 32 (hi/lo split)
        #pragma unroll
        for (int i = 0; i < 4; i++) {
            int idx = tid + i * 256;           // 1024 float4
            int r = idx >> 3, c = (idx & 7) * 4;
            float4 v = *(const float4*)(X + (size_t)(m0 + r) * DM + kc + c);
            float hx = tf32_rn(v.x), hy = tf32_rn(v.y), hz = tf32_rn(v.z), hw = tf32_rn(v.w);
            int o = r * PG_P + c;
            Xh[o] = hx; Xh[o+1] = hy; Xh[o+2] = hz; Xh[o+3] = hw;
            Xl[o]   = tf32_rn(v.x - hx);
            Xl[o+1] = tf32_rn(v.y - hy);
            Xl[o+2] = tf32_rn(v.z - hz);
            Xl[o+3] = tf32_rn(v.w - hw);
        }
        // W tile: 64 x 32 (hi only)
        #pragma unroll
        for (int i = 0; i < 2; i++) {
            int idx = tid + i * 256;           // 512 float4
            int r = idx >> 3, c = (idx & 7) * 4;
            float4 v = *(const float4*)(W + (size_t)(n0 + r) * DM + kc + c);
            int o = r * PG_P + c;
            Wh[o]   = tf32_rn(v.x);
            Wh[o+1] = tf32_rn(v.y);
            Wh[o+2] = tf32_rn(v.z);
            Wh[o+3] = tf32_rn(v.w);
        }
        __syncthreads();

        #pragma unroll
        for (int ks = 0; ks < 4; ks++) {
            const int k0 = ks * 8;
            uint32_t ah[4], al[4];
            int a0 = (wid * 16 + gr) * PG_P + k0 + gc;
            ah[0] = __float_as_uint(Xh[a0]);
            ah[1] = __float_as_uint(Xh[a0 + 8 * PG_P]);
            ah[2] = __float_as_uint(Xh[a0 + 4]);
            ah[3] = __float_as_uint(Xh[a0 + 8 * PG_P + 4]);
            al[0] = __float_as_uint(Xl[a0]);
            al[1] = __float_as_uint(Xl[a0 + 8 * PG_P]);
            al[2] = __float_as_uint(Xl[a0 + 4]);
            al[3] = __float_as_uint(Xl[a0 + 8 * PG_P + 4]);
            #pragma unroll
            for (int t = 0; t < 8; t++) {
                int br = (t * 8 + gr) * PG_P + k0 + gc;
                uint32_t bh0 = __float_as_uint(Wh[br]);
                uint32_t bh1 = __float_as_uint(Wh[br + 4]);
                mma_tf32(acc[t], ah, bh0, bh1);
                mma_tf32(acc[t], al, bh0, bh1);
            }
        }
    }

    // epilogue: C layout c0/c1 -> (row gr, cols 2gc,2gc+1), c2/c3 -> row gr+8
    const int r0 = m0 + wid * 16 + gr;
    #pragma unroll
    for (int t = 0; t < 8; t++) {
        int col = n0 + t * 8 + gc * 2;
        float b0v = bias[col], b1v = bias[col + 1];
        float2 v0 = make_float2(acc[t][0] + b0v, acc[t][1] + b1v);
        float2 v1 = make_float2(acc[t][2] + b0v, acc[t][3] + b1v);
        if (scatter) {
            int hh = col >> 6, d = col & 63;
            int b_ = r0 >> 11, s_ = r0 & (SEQ - 1);
            *(float2*)(out + ((size_t)(b_ * HEADS + hh) * SEQ + s_) * DK + d) = v0;
            int r1 = r0 + 8;
            b_ = r1 >> 11; s_ = r1 & (SEQ - 1);
            *(float2*)(out + ((size_t)(b_ * HEADS + hh) * SEQ + s_) * DK + d) = v1;
        } else {
            *(float2*)(out + (size_t)r0 * DM + col) = v0;
            *(float2*)(out + (size_t)(r0 + 8) * DM + col) = v1;
        }
    }
}

__global__ void __launch_bounds__(256, 4) qkv_gemm_kernel(
    const float* __restrict__ xq, const float* __restrict__ xk, const float* __restrict__ xv,
    const float* __restrict__ Wq, const float* __restrict__ Wk, const float* __restrict__ Wv,
    const float* __restrict__ bq, const float* __restrict__ bk, const float* __restrict__ bv)
{
    extern __shared__ float smf[];
    const float* X; const float* W; const float* bias; float* out;
    if (blockIdx.z == 0)      { X = xq; W = Wq; bias = bq; out = g_q; }
    else if (blockIdx.z == 1) { X = xk; W = Wk; bias = bk; out = g_k; }
    else                      { X = xv; W = Wv; bias = bv; out = g_v; }
    gemm_mma_body(X, W, bias, out, 1, smf);
}

__global__ void __launch_bounds__(256, 4) out_gemm_kernel(
    const float* __restrict__ Wo, const float* __restrict__ bo, float* __restrict__ out)
{
    extern __shared__ float smf[];
    gemm_mma_body(g_attn, Wo, bo, out, 0, smf);
}

// ============================================================
// Flash attention with mma.sync tf32.
// BQ=128, BK=64, D=64. 8 warps, each m16 x all 64 cols.
// QK^T: 2-mma split (Q hi/lo exact, K single-rounded).
// PV:   1-mma; P transposed C-frag -> A-frag via shfl (no smem).
// smem: Qh+Ql+Kh+V = 103KB -> 2 CTAs/SM.
// ============================================================
#define AT_PQ 68
#define AT_PK 68
#define AT_PV 72
#define AT_QH 0
#define AT_QL 8704
#define AT_KH 17408
#define AT_V  21760
#define AT_FLOATS 26368
#define AT_DYN (AT_FLOATS * 4)

__global__ void __launch_bounds__(256, 2) attn_kernel()
{
    extern __shared__ float sm[];
    float* Qh = sm + AT_QH;
    float* Ql = sm + AT_QL;
    float* Kh = sm + AT_KH;
    float* Vs = sm + AT_V;

    const int qb = blockIdx.x;
    const int h  = blockIdx.y;
    const int b  = blockIdx.z;

    const float* Q = g_q + (size_t)(b * HEADS + h) * SEQ * DK;
    const float* K = g_k + (size_t)(b * HEADS + h) * SEQ * DK;
    const float* V = g_v + (size_t)(b * HEADS + h) * SEQ * DK;

    const int tid = threadIdx.x;
    const int wid = tid >> 5, lane = tid & 31;
    const int gr = lane >> 2, gc = lane & 3;
    const int mrow0 = wid * 16;
    // P transpose shuffle sources
    const int lane_src  = (lane & ~3) | (gc >> 1);
    const int lane_src2 = lane_src + 2;
    const bool odd = (gc & 1);

    // load Q tile (128 x 64) split hi/lo
    #pragma unroll
    for (int i = 0; i < 8; i++) {
        int idx = tid + i * 256;             // 2048 float4
        int r = idx >> 4, c = (idx & 15) * 4;
        float4 v = *(const float4*)(Q + (size_t)(qb * 128 + r) * DK + c);
        float hx = tf32_rn(v.x), hy = tf32_rn(v.y), hz = tf32_rn(v.z), hw = tf32_rn(v.w);
        int o = r * AT_PQ + c;
        Qh[o] = hx; Qh[o+1] = hy; Qh[o+2] = hz; Qh[o+3] = hw;
        Ql[o]   = tf32_rn(v.x - hx);
        Ql[o+1] = tf32_rn(v.y - hy);
        Ql[o+2] = tf32_rn(v.z - hz);
        Ql[o+3] = tf32_rn(v.w - hw);
    }

    float mrow[2] = { -INFINITY, -INFINITY };
    float lrow[2] = { 0.f, 0.f };
    float o_acc[8][4] = {};

    for (int kb = 0; kb < SEQ / 64; kb++) {
        __syncthreads();   // all warps finished reading K/V of prev iter
        // load K (hi only) and V tiles: 64 x 64 each
        #pragma unroll
        for (int i = 0; i < 4; i++) {
            int idx = tid + i * 256;         // 1024 float4
            int r = idx >> 4, c = (idx & 15) * 4;
            float4 kv = *(const float4*)(K + (size_t)(kb * 64 + r) * DK + c);
            int ok = r * AT_PK + c;
            Kh[ok]   = tf32_rn(kv.x);
            Kh[ok+1] = tf32_rn(kv.y);
            Kh[ok+2] = tf32_rn(kv.z);
            Kh[ok+3] = tf32_rn(kv.w);
            float4 vv = *(const float4*)(V + (size_t)(kb * 64 + r) * DK + c);
            int ov = r * AT_PV + c;
            Vs[ov]   = tf32_rn(vv.x);
            Vs[ov+1] = tf32_rn(vv.y);
            Vs[ov+2] = tf32_rn(vv.z);
            Vs[ov+3] = tf32_rn(vv.w);
        }
        __syncthreads();

        // ---- scores: S = Q K^T (2-mma split over D=64) ----
        float s_acc[8][4] = {};
        #pragma unroll
        for (int ks = 0; ks < 8; ks++) {
            const int k0 = ks * 8;
            uint32_t ah[4], al[4];
            int a0 = (mrow0 + gr) * AT_PQ + k0 + gc;
            ah[0] = __float_as_uint(Qh[a0]);
            ah[1] = __float_as_uint(Qh[a0 + 8 * AT_PQ]);
            ah[2] = __float_as_uint(Qh[a0 + 4]);
            ah[3] = __float_as_uint(Qh[a0 + 8 * AT_PQ + 4]);
            al[0] = __float_as_uint(Ql[a0]);
            al[1] = __float_as_uint(Ql[a0 + 8 * AT_PQ]);
            al[2] = __float_as_uint(Ql[a0 + 4]);
            al[3] = __float_as_uint(Ql[a0 + 8 * AT_PQ + 4]);
            #pragma unroll
            for (int t = 0; t < 8; t++) {
                int br = (t * 8 + gr) * AT_PK + k0 + gc;
                uint32_t bh0 = __float_as_uint(Kh[br]);
                uint32_t bh1 = __float_as_uint(Kh[br + 4]);
                mma_tf32(s_acc[t], ah, bh0, bh1);
                mma_tf32(s_acc[t], al, bh0, bh1);
            }
        }

        // ---- scale + diag mask + online softmax ----
        const int qg0 = qb * 128 + mrow0 + gr;
        const int qg1 = qg0 + 8;
        float mx0 = -INFINITY, mx1 = -INFINITY;
        #pragma unroll
        for (int t = 0; t < 8; t++) {
            #pragma unroll
            for (int j = 0; j < 2; j++) {
                int colg = kb * 64 + t * 8 + gc * 2 + j;
                float v0 = s_acc[t][j] * 0.125f;
                if (colg == qg0) v0 = NEGV;
                s_acc[t][j] = v0;
                mx0 = fmaxf(mx0, v0);
                float v1 = s_acc[t][j + 2] * 0.125f;
                if (colg == qg1) v1 = NEGV;
                s_acc[t][j + 2] = v1;
                mx1 = fmaxf(mx1, v1);
            }
        }
        mx0 = fmaxf(mx0, __shfl_xor_sync(0xffffffffu, mx0, 1));
        mx0 = fmaxf(mx0, __shfl_xor_sync(0xffffffffu, mx0, 2));
        mx1 = fmaxf(mx1, __shfl_xor_sync(0xffffffffu, mx1, 1));
        mx1 = fmaxf(mx1, __shfl_xor_sync(0xffffffffu, mx1, 2));

        float mn0 = fmaxf(mrow[0], mx0);
        float mn1 = fmaxf(mrow[1], mx1);
        float al0 = (mrow[0] == -INFINITY) ? 0.f : __expf(mrow[0] - mn0);
        float al1 = (mrow[1] == -INFINITY) ? 0.f : __expf(mrow[1] - mn1);

        float rs0 = 0.f, rs1 = 0.f;
        #pragma unroll
        for (int t = 0; t < 8; t++) {
            float p00 = __expf(s_acc[t][0] - mn0);
            float p01 = __expf(s_acc[t][1] - mn0);
            float p10 = __expf(s_acc[t][2] - mn1);
            float p11 = __expf(s_acc[t][3] - mn1);
            rs0 += p00 + p01;
            rs1 += p10 + p11;
            // keep P in registers as tf32 (C-fragment layout)
            s_acc[t][0] = tf32_rn(p00);
            s_acc[t][1] = tf32_rn(p01);
            s_acc[t][2] = tf32_rn(p10);
            s_acc[t][3] = tf32_rn(p11);
        }
        rs0 += __shfl_xor_sync(0xffffffffu, rs0, 1);
        rs0 += __shfl_xor_sync(0xffffffffu, rs0, 2);
        rs1 += __shfl_xor_sync(0xffffffffu, rs1, 1);
        rs1 += __shfl_xor_sync(0xffffffffu, rs1, 2);

        lrow[0] = lrow[0] * al0 + rs0;
        lrow[1] = lrow[1] * al1 + rs1;
        mrow[0] = mn0;
        mrow[1] = mn1;
        #pragma unroll
        for (int t = 0; t < 8; t++) {
            o_acc[t][0] *= al0; o_acc[t][1] *= al0;
            o_acc[t][2] *= al1; o_acc[t][3] *= al1;
        }

        // ---- O += P @ V  (P transposed C->A frag via shfl) ----
        #pragma unroll
        for (int ks = 0; ks < 8; ks++) {
            // A frag: rows gr/gr+8, cols ks*8 + gc / gc+4
            float v00 = __shfl_sync(0xffffffffu, s_acc[ks][0], lane_src);
            float v01 = __shfl_sync(0xffffffffu, s_acc[ks][1], lane_src);
            float v10 = __shfl_sync(0xffffffffu, s_acc[ks][2], lane_src);
            float v11 = __shfl_sync(0xffffffffu, s_acc[ks][3], lane_src);
            float w00 = __shfl_sync(0xffffffffu, s_acc[ks][0], lane_src2);
            float w01 = __shfl_sync(0xffffffffu, s_acc[ks][1], lane_src2);
            float w10 = __shfl_sync(0xffffffffu, s_acc[ks][2], lane_src2);
            float w11 = __shfl_sync(0xffffffffu, s_acc[ks][3], lane_src2);
            uint32_t a[4];
            a[0] = __float_as_uint(odd ? v01 : v00);
            a[1] = __float_as_uint(odd ? v11 : v10);
            a[2] = __float_as_uint(odd ? w01 : w00);
            a[3] = __float_as_uint(odd ? w11 : w10);
            const int k0 = ks * 8;
            #pragma unroll
            for (int t = 0; t < 8; t++) {
                int vr = (k0 + gc) * AT_PV + t * 8 + gr;
                uint32_t b0 = __float_as_uint(Vs[vr]);
                uint32_t b1 = __float_as_uint(Vs[vr + 4 * AT_PV]);
                mma_tf32(o_acc[t], a, b0, b1);
            }
        }
    }

    // ---- finalize ----
    float inv0 = 1.f / lrow[0];
    float inv1 = 1.f / lrow[1];
    int s0 = qb * 128 + mrow0 + gr;
    #pragma unroll
    for (int t = 0; t < 8; t++) {
        int d = t * 8 + gc * 2;
        *(float2*)(g_attn + (size_t)(b * SEQ + s0) * DM + h * DK + d) =
            make_float2(o_acc[t][0] * inv0, o_acc[t][1] * inv0);
        *(float2*)(g_attn + (size_t)(b * SEQ + s0 + 8) * DM + h * DK + d) =
            make_float2(o_acc[t][2] * inv1, o_acc[t][3] * inv1);
    }
}

// ============================================================
extern "C" void kernel_launch(void* const* d_in, const int* in_sizes, int n_in,
                              void* d_out, int out_size)
{
    const float* q  = (const float*)d_in[0];
    const float* k  = (const float*)d_in[1];
    const float* v  = (const float*)d_in[2];
    const float* Wq = (const float*)d_in[3];
    const float* bq = (const float*)d_in[4];
    const float* Wk = (const float*)d_in[5];
    const float* bk = (const float*)d_in[6];
    const float* Wv = (const float*)d_in[7];
    const float* bv = (const float*)d_in[8];
    const float* Wo = (const float*)d_in[9];
    const float* bo = (const float*)d_in[10];
    float* out = (float*)d_out;

    cudaFuncSetAttribute(attn_kernel, cudaFuncAttributeMaxDynamicSharedMemorySize, AT_DYN);
    cudaFuncSetAttribute(qkv_gemm_kernel, cudaFuncAttributeMaxDynamicSharedMemorySize, PG_DYN);
    cudaFuncSetAttribute(out_gemm_kernel, cudaFuncAttributeMaxDynamicSharedMemorySize, PG_DYN);

    qkv_gemm_kernel<<<dim3(DM/64, ROWS/128, 3), 256, PG_DYN>>>(q, k, v, Wq, Wk, Wv, bq, bk, bv);
    attn_kernel<<<dim3(SEQ/128, HEADS, BATCH), 256, AT_DYN>>>();
    out_gemm_kernel<<<dim3(DM/64, ROWS/128, 1), 256, PG_DYN>>>(Wo, bo, out);
}